// round 11
// baseline (speedup 1.0000x reference)
#include <cuda_runtime.h>
#include <cstdint>

#define BS      512
#define DIM     128
#define POS_K   32
#define NUM_NEG 1024
#define INV_TEMP (1.0f / 0.07f)

#define NBLK    256                   // exactly one resident wave (2/SM)
#define D_ST    3                     // per-warp ring depth
#define NPH     4                     // row-range phases

// Output layout (flattened tuple, float32):
#define O0 0          // inst_v2a_pos [512,1]
#define O1 512        // inst_v2a_neg [512,1024]
#define O2 524800     // inst_a2v_pos [512,1]
#define O3 525312     // inst_a2v_neg [512,1024]
#define O4 1049600    // pos_v2v_pos  [512,32]
#define O5 1065984    // pos_v2v_neg  [512,1024]
#define O6 1590272    // pos_a2a_pos  [512,32]
#define O7 1606656    // pos_a2a_neg  [512,1024]

#define FULL 0xffffffffu

__device__ int g_bar[8];

__global__ void reset_bar_kernel() {
    if (threadIdx.x < 8) g_bar[threadIdx.x] = 0;
}

__device__ __forceinline__ float warp_sum(float x) {
#pragma unroll
    for (int o = 16; o; o >>= 1) x += __shfl_xor_sync(FULL, x, o);
    return x;
}

__device__ __forceinline__ float dot4(float4 x, float4 y) {
    return x.x * y.x + x.y * y.y + x.z * y.z + x.w * y.w;
}

__device__ __forceinline__ void grp8_sum2(float& a, float& b) {
#pragma unroll
    for (int o = 4; o; o >>= 1) {
        a += __shfl_xor_sync(FULL, a, o);
        b += __shfl_xor_sync(FULL, b, o);
    }
}

__device__ __forceinline__ void cp_async16(uint32_t dst_smem, const void* src) {
    asm volatile("cp.async.cg.shared.global [%0], [%1], 16;\n"
                 :: "r"(dst_smem), "l"(src) : "memory");
}
__device__ __forceinline__ void cp_commit() {
    asm volatile("cp.async.commit_group;\n" ::: "memory");
}
template <int N>
__device__ __forceinline__ void cp_wait() {
    asm volatile("cp.async.wait_group %0;\n" :: "n"(N) : "memory");
}

// grid-wide barrier: safe because all NBLK blocks are co-resident (one wave)
__device__ __forceinline__ void grid_bar(int k) {
    __syncthreads();
    if (threadIdx.x == 0) {
        atomicAdd(&g_bar[k], 1);
        while (atomicAdd(&g_bar[k], 0) < NBLK) __nanosleep(100);
    }
    __syncthreads();
}

__global__ __launch_bounds__(256, 2)
void avid_cma_kernel(const float* __restrict__ video,
                     const float* __restrict__ audio,
                     const float4* __restrict__ m1,
                     const float4* __restrict__ m2,
                     const int* __restrict__ y,
                     const int* __restrict__ pos_idx,
                     const int* __restrict__ neg_idx,
                     float* __restrict__ out)
{
    extern __shared__ char ring[];              // 8 warps * D_ST * 2048 = 48 KB
    __shared__ uint32_t kbuf[NUM_NEG];          // 4 KB (per-rep scratch)
    __shared__ uint32_t sorted[2][NUM_NEG];     // 8 KB
    __shared__ int      counts[64];
    __shared__ int      obase[64];
    __shared__ int      ocur[64];
    __shared__ int      soff[2][NPH + 1];
    __shared__ float4   sv[2][32];
    __shared__ float4   sa[2][32];
    __shared__ float    sout[2][4][NUM_NEG];    // 32 KB output staging

    const int tid  = threadIdx.x;
    const int lane = tid & 31;
    const int w    = tid >> 5;                  // 8 warps
    const int c    = lane & 7;
    const int r    = lane >> 3;
    char* const wring = ring + (size_t)w * (D_ST * 2048);

    // ---- normalize all 4 fresh vectors (warps 0..3) ----
    if (w < 4) {
        const int rr = w >> 1;
        const int bb = blockIdx.x + rr * NBLK;
        const float* srcv = (w & 1) ? audio : video;
        float4 x = reinterpret_cast<const float4*>(srcv)[bb * 32 + lane];
        float ss = warp_sum(dot4(x, x));
        float inv = 1.0f / fmaxf(sqrtf(ss), 1e-12f);
        float4 nv = make_float4(x.x * inv, x.y * inv, x.z * inv, x.w * inv);
        if (w & 1) sa[rr][lane] = nv; else sv[rr][lane] = nv;
    }

    // ---- bucket-sort both reps' 1024 indices (64 buckets, row>>13) ----
    for (int rep = 0; rep < 2; ++rep) {
        const int b = blockIdx.x + rep * NBLK;
        for (int i = tid; i < NUM_NEG; i += 256) {
            const uint32_t row = (uint32_t)__ldg(neg_idx + (size_t)b * NUM_NEG + i);
            kbuf[i] = (row << 10) | (uint32_t)i;
        }
        if (tid < 64) counts[tid] = 0;
        __syncthreads();
        for (int i = tid; i < NUM_NEG; i += 256)
            atomicAdd(&counts[kbuf[i] >> 23], 1);
        __syncthreads();
        if (tid == 0) {
            int acc = 0;
#pragma unroll
            for (int k = 0; k < 64; ++k) { obase[k] = acc; ocur[k] = acc; acc += counts[k]; }
        }
        __syncthreads();
        for (int i = tid; i < NUM_NEG; i += 256) {
            const uint32_t k2 = kbuf[i];
            const int p = atomicAdd(&ocur[k2 >> 23], 1);
            sorted[rep][p] = k2;
        }
        if (tid <= NPH) soff[rep][tid] = (tid < NPH) ? obase[tid * 16] : NUM_NEG;
        __syncthreads();
    }

    // ---- pos + self dots for both reps (direct LDG) ----
    for (int rep = 0; rep < 2; ++rep) {
        const int bp = blockIdx.x + rep * NBLK;
        const float4 v0 = sv[rep][c], v1 = sv[rep][c + 8], v2 = sv[rep][c + 16], v3 = sv[rep][c + 24];
        const float4 a0 = sa[rep][c], a1 = sa[rep][c + 8], a2 = sa[rep][c + 16], a3 = sa[rep][c + 24];
        const int j  = w * 4 + r;
        const int pi = __ldg(pos_idx + (size_t)bp * POS_K + j);
        const float4* p1 = m1 + (size_t)pi * 32 + c;
        const float4* p2 = m2 + (size_t)pi * 32 + c;
        float dvv = dot4(p1[0], v0) + dot4(p1[8], v1) + dot4(p1[16], v2) + dot4(p1[24], v3);
        float daa = dot4(p2[0], a0) + dot4(p2[8], a1) + dot4(p2[16], a2) + dot4(p2[24], a3);
        grp8_sum2(dvv, daa);
        if (c == 0) {
            out[O4 + (size_t)bp * POS_K + j] = dvv * INV_TEMP;
            out[O6 + (size_t)bp * POS_K + j] = daa * INV_TEMP;
        }
        if (w == 0 && r < 2) {
            const int yi = __ldg(y + bp);
            const float4* p = (r == 0 ? m1 : m2) + (size_t)yi * 32 + c;
            float d;
            if (r == 0) d = dot4(p[0], a0) + dot4(p[8], a1) + dot4(p[16], a2) + dot4(p[24], a3);
            else        d = dot4(p[0], v0) + dot4(p[8], v1) + dot4(p[16], v2) + dot4(p[24], v3);
#pragma unroll
            for (int o = 4; o; o >>= 1) d += __shfl_xor_sync(0x0000ffffu, d, o);
            if (c == 0) {
                if (r == 0) out[O2 + bp] = d * INV_TEMP;
                else        out[O0 + bp] = d * INV_TEMP;
            }
        }
    }

    // ---- phased sorted sweep: 4 row-range phases, grid barrier between ----
    for (int ph = 0; ph < NPH; ++ph) {
        for (int rep = 0; rep < 2; ++rep) {
            const int lo = soff[rep][ph];
            const int hi = soff[rep][ph + 1];
            const int n  = hi - lo;
            if (n <= 0) continue;

            const float4 v0 = sv[rep][c], v1 = sv[rep][c + 8], v2 = sv[rep][c + 16], v3 = sv[rep][c + 24];
            const float4 a0 = sa[rep][c], a1 = sa[rep][c + 8], a2 = sa[rep][c + 16], a3 = sa[rep][c + 24];
            const int S = (n + 15) >> 4;         // stages of 16 refs (block-wide)

            // NOTE: inner variable name g_loc must NOT match any macro argument
            // expression (the R9/R10 bug was `const int g = (g);` self-init).
#define ISSUE(gexp)                                                            \
            do {                                                               \
                const int g_loc = (gexp);                                      \
                _Pragma("unroll")                                              \
                for (int i = 0; i < 4; ++i) {                                  \
                    int p = lo + g_loc * 16 + w * 2 + (i >> 1);                \
                    if (p > hi - 1) p = hi - 1;                                \
                    const int ni = (int)(sorted[rep][p] >> 10);                \
                    const float4* src = ((i & 1) ? m2 : m1) + (size_t)ni * 32 + lane; \
                    uint32_t dst = (uint32_t)__cvta_generic_to_shared(         \
                        wring + ((g_loc % D_ST) * 2048) + i * 512 + lane * 16);\
                    cp_async16(dst, src);                                      \
                }                                                              \
            } while (0)

            // prologue: commit ONLY when a group is actually issued
#pragma unroll
            for (int g = 0; g < D_ST - 1; ++g) {
                if (g < S) { ISSUE(g); cp_commit(); }
            }

            for (int s = 0; s < S; ++s) {
                const int sn = s + D_ST - 1;
                if (sn < S) {
                    // steady state: >= D_ST-1 real groups pending, none empty
                    cp_wait<D_ST - 2>();         // stage s complete
                    __syncwarp();
                    ISSUE(sn);
                    cp_commit();
                } else {
                    // tail: nothing left to issue -> strict drain
                    cp_wait<0>();
                    __syncwarp();
                }

                const float4* buf = reinterpret_cast<const float4*>(
                    wring + (s % D_ST) * 2048) + (size_t)r * 32;
                const float4 x0 = buf[c], x1 = buf[c + 8], x2 = buf[c + 16], x3 = buf[c + 24];
                float dv = dot4(x0, v0) + dot4(x1, v1) + dot4(x2, v2) + dot4(x3, v3);
                float da = dot4(x0, a0) + dot4(x1, a1) + dot4(x2, a2) + dot4(x3, a3);
                grp8_sum2(dv, da);

                const int pr = lo + s * 16 + w * 2 + (r >> 1);
                if (c == 0 && pr < hi) {
                    const int j = (int)(sorted[rep][pr] & 1023u);
                    if ((r & 1) == 0) {          // m1 row: ·a -> O3, ·v -> O5
                        sout[rep][1][j] = da * INV_TEMP;
                        sout[rep][2][j] = dv * INV_TEMP;
                    } else {                     // m2 row: ·v -> O1, ·a -> O7
                        sout[rep][0][j] = dv * INV_TEMP;
                        sout[rep][3][j] = da * INV_TEMP;
                    }
                }
            }
            __syncwarp();
#undef ISSUE
        }
        if (ph < NPH - 1) grid_bar(ph);
    }

    // ---- coalesced output flush ----
    __syncthreads();
    for (int rep = 0; rep < 2; ++rep) {
        const int b = blockIdx.x + rep * NBLK;
        for (int i = tid; i < NUM_NEG; i += 256) {
            const size_t o = (size_t)b * NUM_NEG + i;
            out[O1 + o] = sout[rep][0][i];
            out[O3 + o] = sout[rep][1][i];
            out[O5 + o] = sout[rep][2][i];
            out[O7 + o] = sout[rep][3][i];
        }
    }
}

extern "C" void kernel_launch(void* const* d_in, const int* in_sizes, int n_in,
                              void* d_out, int out_size)
{
    const float* video = (const float*)d_in[0];
    const float* audio = (const float*)d_in[1];
    const float4* m1   = (const float4*)d_in[2];
    const float4* m2   = (const float4*)d_in[3];
    const int* y       = (const int*)d_in[4];
    const int* pos_idx = (const int*)d_in[5];
    const int* neg_idx = (const int*)d_in[6];
    float* out         = (float*)d_out;

    const int dyn_smem = 8 * D_ST * 2048;   // 48 KB
    cudaFuncSetAttribute(avid_cma_kernel,
                         cudaFuncAttributeMaxDynamicSharedMemorySize, dyn_smem);

    reset_bar_kernel<<<1, 32>>>();
    avid_cma_kernel<<<NBLK, 256, dyn_smem>>>(video, audio, m1, m2, y,
                                             pos_idx, neg_idx, out);
}